// round 8
// baseline (speedup 1.0000x reference)
#include <cuda_runtime.h>
#include <cuda_bf16.h>
#include <cstdint>

#define BB 8
#define SS 1024
#define EE 512
#define HH 8
#define HE 4096
#define MQ 8192

#define BM 128
#define BN 128
#define BKT 16

__device__ float g_Pq[(size_t)MQ * HE];
__device__ float g_Pk[(size_t)MQ * HE];
__device__ float g_Pv[(size_t)MQ * HE];
__device__ float g_E [(size_t)BB * HH * SS * SS];
__device__ float g_F [(size_t)MQ * HE];

__device__ __forceinline__ uint32_t smem_u32(const void* p) {
    uint32_t a;
    asm("{ .reg .u64 t; cvta.to.shared.u64 t, %1; cvt.u32.u64 %0, t; }"
        : "=r"(a) : "l"(p));
    return a;
}

__device__ __forceinline__ uint32_t pk2(__nv_bfloat16 a, __nv_bfloat16 b) {
    return ((uint32_t)__bfloat16_as_ushort(b) << 16) | (uint32_t)__bfloat16_as_ushort(a);
}
__device__ __forceinline__ void split4(float4 v, uint2& hi, uint2& lo) {
    __nv_bfloat16 hx = __float2bfloat16(v.x), hy = __float2bfloat16(v.y);
    __nv_bfloat16 hz = __float2bfloat16(v.z), hw = __float2bfloat16(v.w);
    __nv_bfloat16 lx = __float2bfloat16(v.x - __bfloat162float(hx));
    __nv_bfloat16 ly = __float2bfloat16(v.y - __bfloat162float(hy));
    __nv_bfloat16 lz = __float2bfloat16(v.z - __bfloat162float(hz));
    __nv_bfloat16 lw = __float2bfloat16(v.w - __bfloat162float(hw));
    hi.x = pk2(hx, hy); hi.y = pk2(hz, hw);
    lo.x = pk2(lx, ly); lo.y = pk2(lz, lw);
}

#define MMA16(acc, a, b0, b1) \
    asm volatile("mma.sync.aligned.m16n8k16.row.col.f32.bf16.bf16.f32 " \
        "{%0,%1,%2,%3},{%4,%5,%6,%7},{%8,%9},{%0,%1,%2,%3};" \
        : "+f"((acc)[0]), "+f"((acc)[1]), "+f"((acc)[2]), "+f"((acc)[3]) \
        : "r"((a)[0]), "r"((a)[1]), "r"((a)[2]), "r"((a)[3]), \
          "r"(b0), "r"(b1))

#define LDSM4(r0, r1, r2, r3, addr) \
    asm volatile("ldmatrix.sync.aligned.m8n8.x4.shared.b16 {%0,%1,%2,%3}, [%4];" \
        : "=r"(r0), "=r"(r1), "=r"(r2), "=r"(r3) : "r"(addr))

// ---------------------------------------------------------------------------
// C[128,128] = A[M,K] @ op(B), bf16x3 emulated fp32, m16n8k16 + ldmatrix.
// Smem planes: 128 rows x 8 u32 words (k-pairs); 16B-unit flip on (row & 4).
// ---------------------------------------------------------------------------
template<bool TRANSB, bool HASBIAS>
__device__ __forceinline__ void mma_tile(
    const float* __restrict__ A, int lda,
    const float* __restrict__ B, int ldb,
    float* __restrict__ C, int ldc,
    int K, int m0, int n0, const float* __restrict__ bias)
{
    __shared__ uint32_t AsH[2][BM * 8], AsL[2][BM * 8];
    __shared__ uint32_t BsH[2][BN * 8], BsL[2][BN * 8];

    const int tid  = threadIdx.x;
    const int wid  = tid >> 5;
    const int lane = tid & 31;
    const int wm   = wid & 1;      // 2x4 warp grid; warp tile 64x32
    const int wn   = wid >> 1;
    const int qr   = lane >> 2;
    const int qc   = lane & 3;

    const int arow = tid >> 2;     // 0..63 (+64 second chunk)
    const int ak4  = tid & 3;
    const int bk   = tid & 15;     // TRANSB path
    const int bn4  = tid >> 4;

    // ---- ldmatrix per-lane addresses (stage 0; stage 1 = +4KB) ----
    const int g   = lane >> 3;     // matrix group 0..3
    const int sub = lane & 7;
    uint32_t aaddr[4], baddr[2];
#pragma unroll
    for (int mt = 0; mt < 4; ++mt) {
        int r = wm * 64 + mt * 16 + sub + (g & 1) * 8;
        int w = ((g >> 1) * 4) ^ ((r & 4) ? 4 : 0);
        aaddr[mt] = smem_u32(&AsH[0][r * 8 + w]);
    }
#pragma unroll
    for (int p = 0; p < 2; ++p) {
        int r = wn * 32 + p * 16 + sub + (g >> 1) * 8;
        int w = ((g & 1) * 4) ^ ((r & 4) ? 4 : 0);
        baddr[p] = smem_u32(&BsH[0][r * 8 + w]);
    }
    const uint32_t ALOFF = smem_u32(&AsL[0][0]) - smem_u32(&AsH[0][0]);
    const uint32_t BLOFF = smem_u32(&BsL[0][0]) - smem_u32(&BsH[0][0]);
    const uint32_t STOFF = BM * 8 * 4;    // 4KB per stage

    float acc[4][4][4];
#pragma unroll
    for (int i = 0; i < 4; ++i)
#pragma unroll
        for (int j = 0; j < 4; ++j)
#pragma unroll
            for (int r = 0; r < 4; ++r) acc[i][j][r] = 0.0f;

    float4 ar0, ar1, br0, br1;

    auto load_g = [&](int k0) {
        const float* ap = A + (size_t)(m0 + arow) * lda + k0 + ak4 * 4;
        ar0 = *(const float4*)ap;
        ar1 = *(const float4*)(ap + (size_t)64 * lda);
        if (!TRANSB) {
            const float* bp = B + (size_t)(n0 + arow) * ldb + k0 + ak4 * 4;
            br0 = *(const float4*)bp;
            br1 = *(const float4*)(bp + (size_t)64 * ldb);
        } else {
            const float* bp = B + (size_t)(k0 + bk) * ldb + n0 + bn4 * 4;
            br0 = *(const float4*)bp;
            br1 = *(const float4*)(bp + 64);
        }
    };

    auto store_s = [&](int st) {
        uint2 hi, lo;
        const int w0  = (ak4 * 2) ^ ((arow & 4) ? 4 : 0);
        const int w0b = (ak4 * 2) ^ (((arow + 64) & 4) ? 4 : 0);
        split4(ar0, hi, lo);
        *(uint2*)&AsH[st][arow * 8 + w0] = hi;
        *(uint2*)&AsL[st][arow * 8 + w0] = lo;
        split4(ar1, hi, lo);
        *(uint2*)&AsH[st][(arow + 64) * 8 + w0b] = hi;
        *(uint2*)&AsL[st][(arow + 64) * 8 + w0b] = lo;
        if (!TRANSB) {
            split4(br0, hi, lo);
            *(uint2*)&BsH[st][arow * 8 + w0] = hi;
            *(uint2*)&BsL[st][arow * 8 + w0] = lo;
            split4(br1, hi, lo);
            *(uint2*)&BsH[st][(arow + 64) * 8 + w0b] = hi;
            *(uint2*)&BsL[st][(arow + 64) * 8 + w0b] = lo;
        } else {
            const int wd = bk >> 1, hf = bk & 1;
            const float* s0 = &br0.x;
            const float* s1 = &br1.x;
#pragma unroll
            for (int j = 0; j < 4; ++j) {
                int r0 = bn4 * 4 + j, r1 = r0 + 64;
                int p0 = r0 * 8 + (wd ^ ((r0 & 4) ? 4 : 0));
                int p1 = r1 * 8 + (wd ^ ((r1 & 4) ? 4 : 0));
                __nv_bfloat16 h = __float2bfloat16(s0[j]);
                __nv_bfloat16 l = __float2bfloat16(s0[j] - __bfloat162float(h));
                ((uint16_t*)&BsH[st][p0])[hf] = __bfloat16_as_ushort(h);
                ((uint16_t*)&BsL[st][p0])[hf] = __bfloat16_as_ushort(l);
                h = __float2bfloat16(s1[j]);
                l = __float2bfloat16(s1[j] - __bfloat162float(h));
                ((uint16_t*)&BsH[st][p1])[hf] = __bfloat16_as_ushort(h);
                ((uint16_t*)&BsL[st][p1])[hf] = __bfloat16_as_ushort(l);
            }
        }
    };

    auto compute = [&](int st) {
        const uint32_t so = st ? STOFF : 0;
        uint32_t bh[4][2], bl[4][2], a[4][4];
        // B fragments: one x4 covers two n-tiles (b0,b1 each)
#pragma unroll
        for (int p = 0; p < 2; ++p) {
            LDSM4(bh[2*p][0], bh[2*p][1], bh[2*p+1][0], bh[2*p+1][1], baddr[p] + so);
            LDSM4(bl[2*p][0], bl[2*p][1], bl[2*p+1][0], bl[2*p+1][1], baddr[p] + so + BLOFF);
        }
        // A-hi fragments, then hi*bh + hi*bl
#pragma unroll
        for (int mt = 0; mt < 4; ++mt)
            LDSM4(a[mt][0], a[mt][1], a[mt][2], a[mt][3], aaddr[mt] + so);
#pragma unroll
        for (int mt = 0; mt < 4; ++mt)
#pragma unroll
            for (int nt = 0; nt < 4; ++nt) {
                MMA16(acc[mt][nt], a[mt], bh[nt][0], bh[nt][1]);
                MMA16(acc[mt][nt], a[mt], bl[nt][0], bl[nt][1]);
            }
        // A-lo fragments, lo*bh
#pragma unroll
        for (int mt = 0; mt < 4; ++mt)
            LDSM4(a[mt][0], a[mt][1], a[mt][2], a[mt][3], aaddr[mt] + so + ALOFF);
#pragma unroll
        for (int mt = 0; mt < 4; ++mt)
#pragma unroll
            for (int nt = 0; nt < 4; ++nt)
                MMA16(acc[mt][nt], a[mt], bh[nt][0], bh[nt][1]);
    };

    const int niter = K / BKT;
    load_g(0);
    store_s(0);
    __syncthreads();
    for (int kt = 1; kt < niter; ++kt) {
        load_g(kt * BKT);
        compute((kt - 1) & 1);
        store_s(kt & 1);
        __syncthreads();
    }
    compute((niter - 1) & 1);

#pragma unroll
    for (int mt = 0; mt < 4; ++mt) {
#pragma unroll
        for (int nt = 0; nt < 4; ++nt) {
            int row = m0 + wm * 64 + mt * 16 + qr;
            int col = n0 + wn * 32 + nt * 8 + qc * 2;
            float2 v0, v1;
            v0.x = acc[mt][nt][0]; v0.y = acc[mt][nt][1];
            v1.x = acc[mt][nt][2]; v1.y = acc[mt][nt][3];
            if (HASBIAS) {
                v0.x += bias[col]; v0.y += bias[col + 1];
                v1.x += bias[col]; v1.y += bias[col + 1];
            }
            *(float2*)&C[(size_t)row * ldc + col] = v0;
            *(float2*)&C[(size_t)(row + 8) * ldc + col] = v1;
        }
    }
}

// ---------------------------------------------------------------------------
__global__ void __launch_bounds__(256)
k_gemm_nt(const float* __restrict__ A, int lda,
          const float* __restrict__ B, int ldb,
          float* __restrict__ C, int ldc, int K)
{
    mma_tile<false, false>(A, lda, B, ldb, C, ldc, K,
                           blockIdx.y * BM, blockIdx.x * BN, nullptr);
}

__global__ void __launch_bounds__(256)
k_gemm_nt_bias(const float* __restrict__ A, int lda,
               const float* __restrict__ B, int ldb,
               float* __restrict__ C, int ldc, int K,
               const float* __restrict__ bias)
{
    mma_tile<false, true>(A, lda, B, ldb, C, ldc, K,
                          blockIdx.y * BM, blockIdx.x * BN, bias);
}

__global__ void __launch_bounds__(256)
k_energy(const float* __restrict__ Pq, const float* __restrict__ Pk,
         float* __restrict__ Eng)
{
    const int bh = blockIdx.z;
    const int m0 = blockIdx.y * BM;
    const int n0 = blockIdx.x * BN;
    if (n0 > m0) return;
    const float* Q  = Pq + (size_t)bh * SS * EE;
    const float* Kp = Pk + (size_t)bh * SS * EE;
    float* Cc       = Eng + (size_t)bh * SS * SS;
    mma_tile<false, false>(Q, EE, Kp, EE, Cc, SS, EE, m0, n0, nullptr);
}

__global__ void __launch_bounds__(256)
k_pv(const float* __restrict__ P, const float* __restrict__ Pv,
     float* __restrict__ F)
{
    const int bh = blockIdx.z;
    const int b  = bh >> 3;
    const int h  = bh & 7;
    const int m0 = blockIdx.y * BM;
    const int n0 = blockIdx.x * BN;
    const float* Pp = P  + (size_t)bh * SS * SS;
    const float* V  = Pv + (size_t)bh * SS * EE;
    float* Cc = F + (size_t)b * SS * HE + (size_t)h * EE;
    mma_tile<true, false>(Pp, SS, V, EE, Cc, HE, m0 + BM, m0, n0, nullptr);
}

// Causal softmax, in-place, mask-before-scale (scale = 1/8)
__global__ void k_softmax(float* __restrict__ Eng)
{
    const int i = blockIdx.x;
    float* row = Eng + ((size_t)blockIdx.y * SS + i) * SS;
    const int L = i + 1;
    const int tid = threadIdx.x;

    float r[4];
    float lmax = -1e30f;
#pragma unroll
    for (int t = 0; t < 4; ++t) {
        int j = tid + t * 256;
        if (j < L) { r[t] = row[j]; lmax = fmaxf(lmax, r[t]); }
        else         r[t] = -1e30f;
    }
    __shared__ float red[8];
    for (int o = 16; o; o >>= 1) lmax = fmaxf(lmax, __shfl_xor_sync(0xffffffffu, lmax, o));
    if ((tid & 31) == 0) red[tid >> 5] = lmax;
    __syncthreads();
    if (tid == 0) {
        float m = red[0];
#pragma unroll
        for (int w = 1; w < 8; ++w) m = fmaxf(m, red[w]);
        red[0] = m;
    }
    __syncthreads();
    const float m = red[0];
    __syncthreads();

    float lsum = 0.0f;
#pragma unroll
    for (int t = 0; t < 4; ++t) {
        int j = tid + t * 256;
        if (j < L) { r[t] = __expf((r[t] - m) * 0.125f); lsum += r[t]; }
        else         r[t] = 0.0f;
    }
    for (int o = 16; o; o >>= 1) lsum += __shfl_xor_sync(0xffffffffu, lsum, o);
    if ((tid & 31) == 0) red[tid >> 5] = lsum;
    __syncthreads();
    if (tid == 0) {
        float s = red[0];
#pragma unroll
        for (int w = 1; w < 8; ++w) s += red[w];
        red[0] = s;
    }
    __syncthreads();
    const float inv = 1.0f / red[0];
#pragma unroll
    for (int t = 0; t < 4; ++t) {
        int j = tid + t * 256;
        row[j] = r[t] * inv;
    }
}

// ---------------------------------------------------------------------------
extern "C" void kernel_launch(void* const* d_in, const int* in_sizes, int n_in,
                              void* d_out, int out_size)
{
    (void)in_sizes; (void)n_in; (void)out_size;
    const float* k  = (const float*)d_in[0];
    const float* v  = (const float*)d_in[1];
    const float* q  = (const float*)d_in[2];
    const float* Wk = (const float*)d_in[4];
    const float* Wq = (const float*)d_in[5];
    const float* Wv = (const float*)d_in[6];
    const float* Wo = (const float*)d_in[7];
    const float* bo = (const float*)d_in[8];
    float* out = (float*)d_out;

    float *Pq, *Pk, *Pv, *Em, *F;
    cudaGetSymbolAddress((void**)&Pq, g_Pq);
    cudaGetSymbolAddress((void**)&Pk, g_Pk);
    cudaGetSymbolAddress((void**)&Pv, g_Pv);
    cudaGetSymbolAddress((void**)&Em, g_E);
    cudaGetSymbolAddress((void**)&F,  g_F);

    dim3 blk(256);

    dim3 gp(HE / BN, MQ / BM);
    k_gemm_nt<<<gp, blk>>>(q, EE, Wq, EE, Pq, HE, EE);
    k_gemm_nt<<<gp, blk>>>(k, EE, Wk, EE, Pk, HE, EE);
    k_gemm_nt<<<gp, blk>>>(v, EE, Wv, EE, Pv, HE, EE);

    dim3 ge(SS / BN, SS / BM, BB * HH);
    k_energy<<<ge, blk>>>(Pq, Pk, Em);

    k_softmax<<<dim3(SS, BB * HH), 256>>>(Em);

    dim3 gv(EE / BN, SS / BM, BB * HH);
    k_pv<<<gv, blk>>>(Em, Pv, F);

    dim3 go(EE / BN, MQ / BM);
    k_gemm_nt_bias<<<go, blk>>>(F, HE, Wo, HE, out, EE, HE, bo);
}

// round 9
// speedup vs baseline: 1.3787x; 1.3787x over previous
#include <cuda_runtime.h>
#include <cuda_bf16.h>
#include <cstdint>

#define BB 8
#define SS 1024
#define EE 512
#define HH 8
#define HE 4096
#define MQ 8192

#define BM 128
#define BN 128

__device__ float g_Pq[(size_t)MQ * HE];
__device__ float g_Pk[(size_t)MQ * HE];
__device__ float g_Pv[(size_t)MQ * HE];
__device__ float g_E [(size_t)BB * HH * SS * SS];
__device__ float g_F [(size_t)MQ * HE];

__device__ __forceinline__ uint32_t pk2(__nv_bfloat16 a, __nv_bfloat16 b) {
    return ((uint32_t)__bfloat16_as_ushort(b) << 16) | (uint32_t)__bfloat16_as_ushort(a);
}
__device__ __forceinline__ void split4(float4 v, uint2& hi, uint2& lo) {
    __nv_bfloat16 hx = __float2bfloat16(v.x), hy = __float2bfloat16(v.y);
    __nv_bfloat16 hz = __float2bfloat16(v.z), hw = __float2bfloat16(v.w);
    __nv_bfloat16 lx = __float2bfloat16(v.x - __bfloat162float(hx));
    __nv_bfloat16 ly = __float2bfloat16(v.y - __bfloat162float(hy));
    __nv_bfloat16 lz = __float2bfloat16(v.z - __bfloat162float(hz));
    __nv_bfloat16 lw = __float2bfloat16(v.w - __bfloat162float(hw));
    hi.x = pk2(hx, hy); hi.y = pk2(hz, hw);
    lo.x = pk2(lx, ly); lo.y = pk2(lz, lw);
}

#define MMA16(acc, a, b) \
    asm volatile("mma.sync.aligned.m16n8k16.row.col.f32.bf16.bf16.f32 " \
        "{%0,%1,%2,%3},{%4,%5,%6,%7},{%8,%9},{%0,%1,%2,%3};" \
        : "+f"((acc)[0]), "+f"((acc)[1]), "+f"((acc)[2]), "+f"((acc)[3]) \
        : "r"((a)[0]), "r"((a)[1]), "r"((a)[2]), "r"((a)[3]), \
          "r"((b)[0]), "r"((b)[1]))

// ---------------------------------------------------------------------------
// C[128,128] = A[M,K] @ op(B), bf16x3 emulated fp32 on m16n8k16 tensor cores.
// 4 k16 sub-block buffers (2 stages x 2 subs); one barrier per 32-k.
// Smem planes: 128 rows x 8 u32 words; 16B-unit flip on (row & 4).
// ---------------------------------------------------------------------------
template<bool TRANSB, bool HASBIAS>
__device__ __forceinline__ void mma_tile(
    const float* __restrict__ A, int lda,
    const float* __restrict__ B, int ldb,
    float* __restrict__ C, int ldc,
    int K, int m0, int n0, const float* __restrict__ bias)
{
    __shared__ uint32_t AsH[4][BM * 8], AsL[4][BM * 8];
    __shared__ uint32_t BsH[4][BN * 8], BsL[4][BN * 8];

    const int tid  = threadIdx.x;
    const int wid  = tid >> 5;
    const int lane = tid & 31;
    const int wm   = wid & 1;      // 2x4 warp grid; warp tile 64x32
    const int wn   = wid >> 1;
    const int qr   = lane >> 2;
    const int qc   = lane & 3;
    const int swz  = qr & 4;

    const int arow = tid >> 2;     // 0..63 (+64 second chunk)
    const int ak4  = tid & 3;
    const int bk   = tid & 15;     // TRANSB path
    const int bn4  = tid >> 4;

    float acc[4][4][4];
#pragma unroll
    for (int i = 0; i < 4; ++i)
#pragma unroll
        for (int j = 0; j < 4; ++j)
#pragma unroll
            for (int r = 0; r < 4; ++r) acc[i][j][r] = 0.0f;

    float4 ar0, ar1, br0, br1;

    auto load_g = [&](int k0) {
        const float* ap = A + (size_t)(m0 + arow) * lda + k0 + ak4 * 4;
        ar0 = *(const float4*)ap;
        ar1 = *(const float4*)(ap + (size_t)64 * lda);
        if (!TRANSB) {
            const float* bp = B + (size_t)(n0 + arow) * ldb + k0 + ak4 * 4;
            br0 = *(const float4*)bp;
            br1 = *(const float4*)(bp + (size_t)64 * ldb);
        } else {
            const float* bp = B + (size_t)(k0 + bk) * ldb + n0 + bn4 * 4;
            br0 = *(const float4*)bp;
            br1 = *(const float4*)(bp + 64);
        }
    };

    auto store_s = [&](int bu) {
        uint2 hi, lo;
        const int w0  = (ak4 * 2) ^ ((arow & 4) ? 4 : 0);
        const int w0b = (ak4 * 2) ^ (((arow + 64) & 4) ? 4 : 0);
        split4(ar0, hi, lo);
        *(uint2*)&AsH[bu][arow * 8 + w0] = hi;
        *(uint2*)&AsL[bu][arow * 8 + w0] = lo;
        split4(ar1, hi, lo);
        *(uint2*)&AsH[bu][(arow + 64) * 8 + w0b] = hi;
        *(uint2*)&AsL[bu][(arow + 64) * 8 + w0b] = lo;
        if (!TRANSB) {
            split4(br0, hi, lo);
            *(uint2*)&BsH[bu][arow * 8 + w0] = hi;
            *(uint2*)&BsL[bu][arow * 8 + w0] = lo;
            split4(br1, hi, lo);
            *(uint2*)&BsH[bu][(arow + 64) * 8 + w0b] = hi;
            *(uint2*)&BsL[bu][(arow + 64) * 8 + w0b] = lo;
        } else {
            const int wd = bk >> 1, hf = bk & 1;
            const float* s0 = &br0.x;
            const float* s1 = &br1.x;
#pragma unroll
            for (int j = 0; j < 4; ++j) {
                int r0 = bn4 * 4 + j, r1 = r0 + 64;
                int p0 = r0 * 8 + (wd ^ ((r0 & 4) ? 4 : 0));
                int p1 = r1 * 8 + (wd ^ ((r1 & 4) ? 4 : 0));
                __nv_bfloat16 h = __float2bfloat16(s0[j]);
                __nv_bfloat16 l = __float2bfloat16(s0[j] - __bfloat162float(h));
                ((uint16_t*)&BsH[bu][p0])[hf] = __bfloat16_as_ushort(h);
                ((uint16_t*)&BsL[bu][p0])[hf] = __bfloat16_as_ushort(l);
                h = __float2bfloat16(s1[j]);
                l = __float2bfloat16(s1[j] - __bfloat162float(h));
                ((uint16_t*)&BsH[bu][p1])[hf] = __bfloat16_as_ushort(h);
                ((uint16_t*)&BsL[bu][p1])[hf] = __bfloat16_as_ushort(l);
            }
        }
    };

    auto compute = [&](int bu) {
        const int wA = qc ^ swz, wA2 = (qc + 4) ^ swz;
        uint32_t bh[4][2], bl[4][2];
#pragma unroll
        for (int nt = 0; nt < 4; ++nt) {
            int rb = (wn * 32 + nt * 8 + qr) * 8;
            bh[nt][0] = BsH[bu][rb + wA];  bh[nt][1] = BsH[bu][rb + wA2];
            bl[nt][0] = BsL[bu][rb + wA];  bl[nt][1] = BsL[bu][rb + wA2];
        }
        {
            uint32_t a[4][4];
#pragma unroll
            for (int mt = 0; mt < 4; ++mt) {
                int ra = (wm * 64 + mt * 16 + qr) * 8;
                a[mt][0] = AsH[bu][ra + wA];   a[mt][1] = AsH[bu][ra + 64 + wA];
                a[mt][2] = AsH[bu][ra + wA2];  a[mt][3] = AsH[bu][ra + 64 + wA2];
            }
#pragma unroll
            for (int mt = 0; mt < 4; ++mt)
#pragma unroll
                for (int nt = 0; nt < 4; ++nt) {
                    MMA16(acc[mt][nt], a[mt], bh[nt]);
                    MMA16(acc[mt][nt], a[mt], bl[nt]);
                }
        }
        {
            uint32_t a[4][4];
#pragma unroll
            for (int mt = 0; mt < 4; ++mt) {
                int ra = (wm * 64 + mt * 16 + qr) * 8;
                a[mt][0] = AsL[bu][ra + wA];   a[mt][1] = AsL[bu][ra + 64 + wA];
                a[mt][2] = AsL[bu][ra + wA2];  a[mt][3] = AsL[bu][ra + 64 + wA2];
            }
#pragma unroll
            for (int mt = 0; mt < 4; ++mt)
#pragma unroll
                for (int nt = 0; nt < 4; ++nt)
                    MMA16(acc[mt][nt], a[mt], bh[nt]);
        }
    };

    // k32 pipeline: one barrier per 32-k; each LDG covered by a k16 compute.
    const int nkc = K >> 5;
    load_g(0);  store_s(0);
    load_g(16); store_s(1);
    __syncthreads();
    for (int kc = 1; kc < nkc; ++kc) {
        const int st = (kc & 1) * 2;
        const int pv = ((kc - 1) & 1) * 2;
        load_g(kc * 32);
        compute(pv);
        store_s(st);
        load_g(kc * 32 + 16);
        compute(pv + 1);
        store_s(st + 1);
        __syncthreads();
    }
    const int lp = ((nkc - 1) & 1) * 2;
    compute(lp);
    compute(lp + 1);

#pragma unroll
    for (int mt = 0; mt < 4; ++mt) {
#pragma unroll
        for (int nt = 0; nt < 4; ++nt) {
            int row = m0 + wm * 64 + mt * 16 + qr;
            int col = n0 + wn * 32 + nt * 8 + qc * 2;
            float2 v0, v1;
            v0.x = acc[mt][nt][0]; v0.y = acc[mt][nt][1];
            v1.x = acc[mt][nt][2]; v1.y = acc[mt][nt][3];
            if (HASBIAS) {
                v0.x += bias[col]; v0.y += bias[col + 1];
                v1.x += bias[col]; v1.y += bias[col + 1];
            }
            *(float2*)&C[(size_t)row * ldc + col] = v0;
            *(float2*)&C[(size_t)(row + 8) * ldc + col] = v1;
        }
    }
}

// ---------------------------------------------------------------------------
__global__ void __launch_bounds__(256, 2)
k_gemm_nt(const float* __restrict__ A, int lda,
          const float* __restrict__ B, int ldb,
          float* __restrict__ C, int ldc, int K)
{
    mma_tile<false, false>(A, lda, B, ldb, C, ldc, K,
                           blockIdx.y * BM, blockIdx.x * BN, nullptr);
}

__global__ void __launch_bounds__(256, 2)
k_gemm_nt_bias(const float* __restrict__ A, int lda,
               const float* __restrict__ B, int ldb,
               float* __restrict__ C, int ldc, int K,
               const float* __restrict__ bias)
{
    mma_tile<false, true>(A, lda, B, ldb, C, ldc, K,
                          blockIdx.y * BM, blockIdx.x * BN, bias);
}

__global__ void __launch_bounds__(256, 2)
k_energy(const float* __restrict__ Pq, const float* __restrict__ Pk,
         float* __restrict__ Eng)
{
    const int bh = blockIdx.z;
    const int m0 = blockIdx.y * BM;
    const int n0 = blockIdx.x * BN;
    if (n0 > m0) return;
    const float* Q  = Pq + (size_t)bh * SS * EE;
    const float* Kp = Pk + (size_t)bh * SS * EE;
    float* Cc       = Eng + (size_t)bh * SS * SS;
    mma_tile<false, false>(Q, EE, Kp, EE, Cc, SS, EE, m0, n0, nullptr);
}

__global__ void __launch_bounds__(256, 2)
k_pv(const float* __restrict__ P, const float* __restrict__ Pv,
     float* __restrict__ F)
{
    const int bh = blockIdx.z;
    const int b  = bh >> 3;
    const int h  = bh & 7;
    const int m0 = blockIdx.y * BM;
    const int n0 = blockIdx.x * BN;
    const float* Pp = P  + (size_t)bh * SS * SS;
    const float* V  = Pv + (size_t)bh * SS * EE;
    float* Cc = F + (size_t)b * SS * HE + (size_t)h * EE;
    mma_tile<true, false>(Pp, SS, V, EE, Cc, HE, m0 + BM, m0, n0, nullptr);
}

// Causal softmax, in-place, mask-before-scale (scale = 1/8)
__global__ void k_softmax(float* __restrict__ Eng)
{
    const int i = blockIdx.x;
    float* row = Eng + ((size_t)blockIdx.y * SS + i) * SS;
    const int L = i + 1;
    const int tid = threadIdx.x;

    float r[4];
    float lmax = -1e30f;
#pragma unroll
    for (int t = 0; t < 4; ++t) {
        int j = tid + t * 256;
        if (j < L) { r[t] = row[j]; lmax = fmaxf(lmax, r[t]); }
        else         r[t] = -1e30f;
    }
    __shared__ float red[8];
    for (int o = 16; o; o >>= 1) lmax = fmaxf(lmax, __shfl_xor_sync(0xffffffffu, lmax, o));
    if ((tid & 31) == 0) red[tid >> 5] = lmax;
    __syncthreads();
    if (tid == 0) {
        float m = red[0];
#pragma unroll
        for (int w = 1; w < 8; ++w) m = fmaxf(m, red[w]);
        red[0] = m;
    }
    __syncthreads();
    const float m = red[0];
    __syncthreads();

    float lsum = 0.0f;
#pragma unroll
    for (int t = 0; t < 4; ++t) {
        int j = tid + t * 256;
        if (j < L) { r[t] = __expf((r[t] - m) * 0.125f); lsum += r[t]; }
        else         r[t] = 0.0f;
    }
    for (int o = 16; o; o >>= 1) lsum += __shfl_xor_sync(0xffffffffu, lsum, o);
    if ((tid & 31) == 0) red[tid >> 5] = lsum;
    __syncthreads();
    if (tid == 0) {
        float s = red[0];
#pragma unroll
        for (int w = 1; w < 8; ++w) s += red[w];
        red[0] = s;
    }
    __syncthreads();
    const float inv = 1.0f / red[0];
#pragma unroll
    for (int t = 0; t < 4; ++t) {
        int j = tid + t * 256;
        row[j] = r[t] * inv;
    }
}

// ---------------------------------------------------------------------------
extern "C" void kernel_launch(void* const* d_in, const int* in_sizes, int n_in,
                              void* d_out, int out_size)
{
    (void)in_sizes; (void)n_in; (void)out_size;
    const float* k  = (const float*)d_in[0];
    const float* v  = (const float*)d_in[1];
    const float* q  = (const float*)d_in[2];
    const float* Wk = (const float*)d_in[4];
    const float* Wq = (const float*)d_in[5];
    const float* Wv = (const float*)d_in[6];
    const float* Wo = (const float*)d_in[7];
    const float* bo = (const float*)d_in[8];
    float* out = (float*)d_out;

    float *Pq, *Pk, *Pv, *Em, *F;
    cudaGetSymbolAddress((void**)&Pq, g_Pq);
    cudaGetSymbolAddress((void**)&Pk, g_Pk);
    cudaGetSymbolAddress((void**)&Pv, g_Pv);
    cudaGetSymbolAddress((void**)&Em, g_E);
    cudaGetSymbolAddress((void**)&F,  g_F);

    dim3 blk(256);

    dim3 gp(HE / BN, MQ / BM);
    k_gemm_nt<<<gp, blk>>>(q, EE, Wq, EE, Pq, HE, EE);
    k_gemm_nt<<<gp, blk>>>(k, EE, Wk, EE, Pk, HE, EE);
    k_gemm_nt<<<gp, blk>>>(v, EE, Wv, EE, Pv, HE, EE);

    dim3 ge(SS / BN, SS / BM, BB * HH);
    k_energy<<<ge, blk>>>(Pq, Pk, Em);

    k_softmax<<<dim3(SS, BB * HH), 256>>>(Em);

    dim3 gv(EE / BN, SS / BM, BB * HH);
    k_pv<<<gv, blk>>>(Em, Pv, F);

    dim3 go(EE / BN, MQ / BM);
    k_gemm_nt_bias<<<go, blk>>>(F, HE, Wo, HE, out, EE, HE, bo);
}